// round 7
// baseline (speedup 1.0000x reference)
#include <cuda_runtime.h>

#define B    32
#define D    1024   // CTX_DIM
#define C    2048   // CTX_SIZE
#define H    1024   // HID
#define HC   32     // h-chunks in kernel A
#define HCH  (H/HC) // 32 h per chunk
#define CCH  16     // context columns per chunk
#define GCH  8      // chunks per CTA (flash-style running accumulation)
#define NCHB (C/(CCH*GCH))  // 16 CTA-columns per batch

// ---- scratch (no allocations allowed) ----
__device__ float g_pv[HC * B * D];       // 4 MB  partial v
__device__ float g_v[B * D];             // 128 KB v[b,d]
__device__ float g_pacc[B * NCHB * D];   // 2 MB per-CTA weighted partial sums
__device__ float g_pm[B * NCHB];         // per-CTA max
__device__ float g_pz[B * NCHB];         // per-CTA Z (unnormalized)
__device__ float g_ctx[B * D];           // final normalized context
__device__ float g_inv[B];               // (unused placeholder)

// ---------- Kernel A: partial v[b,d] = sum_{h in chunk} W[h,d]*hidden[b,h] ----------
__global__ void vpart_kernel(const float* __restrict__ W, const float* __restrict__ hid) {
    __shared__ float sh[B][HCH];
    const int tid = threadIdx.x;                 // 128 threads
    const int d   = blockIdx.x * 128 + tid;      // 8 d-tiles
    const int h0  = blockIdx.y * HCH;            // 32 h-chunks
    for (int i = tid; i < B * HCH; i += 128) {
        int b = i / HCH, h = i % HCH;
        sh[b][h] = hid[b * H + h0 + h];
    }
    __syncthreads();
    float acc[B];
#pragma unroll
    for (int b = 0; b < B; b++) acc[b] = 0.f;
#pragma unroll 8
    for (int h = 0; h < HCH; h++) {
        float w = W[(size_t)(h0 + h) * D + d];
#pragma unroll
        for (int b = 0; b < B; b++) acc[b] += w * sh[b][h];
    }
    float* outp = g_pv + (size_t)blockIdx.y * (B * D);
#pragma unroll
    for (int b = 0; b < B; b++) outp[b * D + d] = acc[b];
}

// ---------- Kernel B: reduce partials -> g_v (float4, MLP 8) ----------
__global__ void vreduce_kernel() {
    int i = blockIdx.x * 256 + threadIdx.x;      // 32 blocks x 256 -> 8192 float4
    const float4* src = reinterpret_cast<const float4*>(g_pv) + i;
    float4 s = make_float4(0.f, 0.f, 0.f, 0.f);
#pragma unroll 8
    for (int hc = 0; hc < HC; hc++) {
        float4 p = src[(size_t)hc * (B * D / 4)];
        s.x += p.x; s.y += p.y; s.z += p.z; s.w += p.w;
    }
    reinterpret_cast<float4*>(g_v)[i] = s;
}

// ---------- Kernel C: 8 chunks/CTA, register double-buffered pipeline ----------
__global__ void __launch_bounds__(512, 1) main_kernel(const float* __restrict__ ctx) {
    __shared__ float red[16 * 16];
    __shared__ float ws[16];
    __shared__ float sm_acc[D];
    __shared__ float m_sm, z_sm;

    const int tid  = threadIdx.x;       // 512
    const int lane = tid & 31;
    const int w    = tid >> 5;          // 0..15
    const int cq   = lane & 3;          // float4 column group 0..3
    const int r    = lane >> 2;         // 0..7
    const int b    = blockIdx.y;
    const int chg  = blockIdx.x;        // 0..NCHB-1

    const int drow = w * 8 + r;         // 0..127
    const float* base0 = ctx + (size_t)b * D * C + (size_t)drow * C
                       + chg * (CCH * GCH) + 4 * cq;

    float vr[8];
#pragma unroll
    for (int i = 0; i < 8; i++)
        vr[i] = __ldg(&g_v[b * D + i * 128 + drow]);

    float accA = 0.f, accB = 0.f;       // running weighted sums for d=tid, tid+512
    float m_run = -1e30f, z_run = 0.f;

    auto loadChunk = [&](float4 (&x)[8], int g) {
        const float* base = base0 + g * CCH;
#pragma unroll
        for (int i = 0; i < 8; i++)
            x[i] = __ldcs(reinterpret_cast<const float4*>(base + (size_t)i * 128 * C));
    };

    auto procChunk = [&](float4 (&x)[8]) {
        // Phase 1: per-column partial scores
        float p0 = 0.f, p1 = 0.f, p2 = 0.f, p3 = 0.f;
#pragma unroll
        for (int i = 0; i < 8; i++) {
            p0 += x[i].x * vr[i];  p1 += x[i].y * vr[i];
            p2 += x[i].z * vr[i];  p3 += x[i].w * vr[i];
        }
#pragma unroll
        for (int o = 4; o <= 16; o <<= 1) {
            p0 += __shfl_xor_sync(0xffffffffu, p0, o);
            p1 += __shfl_xor_sync(0xffffffffu, p1, o);
            p2 += __shfl_xor_sync(0xffffffffu, p2, o);
            p3 += __shfl_xor_sync(0xffffffffu, p3, o);
        }
        if (r == 0) {
            red[w * 16 + 4 * cq + 0] = p0;
            red[w * 16 + 4 * cq + 1] = p1;
            red[w * 16 + 4 * cq + 2] = p2;
            red[w * 16 + 4 * cq + 3] = p3;
        }
        __syncthreads();

        // lanes 0..15: finish 16 scores + chunk softmax stats
        if (tid < 16) {
            float s = 0.f;
#pragma unroll
            for (int q = 0; q < 16; q++) s += red[q * 16 + tid];
            float m = s;
#pragma unroll
            for (int o = 8; o > 0; o >>= 1) m = fmaxf(m, __shfl_xor_sync(0x0000ffffu, m, o));
            float e = __expf(s - m);
            float z = e;
#pragma unroll
            for (int o = 8; o > 0; o >>= 1) z += __shfl_xor_sync(0x0000ffffu, z, o);
            ws[tid] = e;
            if (tid == 0) { m_sm = m; z_sm = z; }
        }
        __syncthreads();

        // Phase 2: weighted column sum from registers
        const float w0 = ws[4 * cq + 0], w1 = ws[4 * cq + 1];
        const float w2 = ws[4 * cq + 2], w3 = ws[4 * cq + 3];
#pragma unroll
        for (int i = 0; i < 8; i++) {
            float t = x[i].x * w0 + x[i].y * w1 + x[i].z * w2 + x[i].w * w3;
            t += __shfl_xor_sync(0xffffffffu, t, 1);
            t += __shfl_xor_sync(0xffffffffu, t, 2);
            if (cq == 0) sm_acc[i * 128 + drow] = t;
        }
        __syncthreads();

        // Running rescale-accumulate
        const float m_g = m_sm, z_g = z_sm;
        const float m_new = fmaxf(m_run, m_g);
        const float alpha = __expf(m_run - m_new);
        const float beta  = __expf(m_g - m_new);
        accA = accA * alpha + sm_acc[tid] * beta;
        accB = accB * alpha + sm_acc[tid + 512] * beta;
        z_run = z_run * alpha + z_g * beta;
        m_run = m_new;
        __syncthreads();   // sm_acc reused next iteration
    };

    float4 xa[8], xb[8];
    loadChunk(xa, 0);
#pragma unroll
    for (int gp = 0; gp < GCH / 2; gp++) {
        loadChunk(xb, 2 * gp + 1);        // prefetch odd chunk
        procChunk(xa);                     // process even chunk (loads for xb in flight)
        if (2 * gp + 2 < GCH) loadChunk(xa, 2 * gp + 2);  // prefetch next even
        procChunk(xb);
    }

    float* dst = g_pacc + (size_t)(b * NCHB + chg) * D;
    dst[tid]       = accA;
    dst[tid + 512] = accB;
    if (tid == 0) { g_pm[b * NCHB + chg] = m_run; g_pz[b * NCHB + chg] = z_run; }
}

// ---------- Kernel D1: single-stage combine -> g_ctx ----------
// grid (B, 8): block handles 128 d's (32 float4) across all 16 chunk entries.
__global__ void combine_kernel() {
    __shared__ float pm[NCHB], pz[NCHB], fsh[NCHB];
    __shared__ float inv_sh;
    __shared__ float4 part[8][32];
    const int b   = blockIdx.x;
    const int ds  = blockIdx.y;            // 0..7  d-slice
    const int tid = threadIdx.x;           // 256
    const int f4  = tid & 31;              // float4 within slice
    const int grp = tid >> 5;              // 0..7 chunk group (2 chunks each)

    if (tid < NCHB) { pm[tid] = g_pm[b * NCHB + tid]; pz[tid] = g_pz[b * NCHB + tid]; }
    __syncthreads();
    if (tid < NCHB) {
        float M = -1e30f;
#pragma unroll
        for (int ch = 0; ch < NCHB; ch++) M = fmaxf(M, pm[ch]);
        fsh[tid] = __expf(pm[tid] - M);
        if (tid == 0) {
            float Z = 0.f;
#pragma unroll
            for (int ch = 0; ch < NCHB; ch++) Z += pz[ch] * __expf(pm[ch] - M);
            inv_sh = 1.0f / Z;
        }
    }
    __syncthreads();

    float4 a = make_float4(0.f, 0.f, 0.f, 0.f);
#pragma unroll
    for (int j = 0; j < 2; j++) {
        int ch = grp * 2 + j;
        float4 p = reinterpret_cast<const float4*>(
            g_pacc + (size_t)(b * NCHB + ch) * D + ds * 128)[f4];
        float f = fsh[ch];
        a.x += p.x * f; a.y += p.y * f; a.z += p.z * f; a.w += p.w * f;
    }
    part[grp][f4] = a;
    __syncthreads();

    if (tid < 32) {
        float4 s = make_float4(0.f, 0.f, 0.f, 0.f);
#pragma unroll
        for (int g = 0; g < 8; g++) {
            float4 p = part[g][tid];
            s.x += p.x; s.y += p.y; s.z += p.z; s.w += p.w;
        }
        const float inv = inv_sh;
        s.x *= inv; s.y *= inv; s.z *= inv; s.w *= inv;
        reinterpret_cast<float4*>(g_ctx + b * D + ds * 128)[tid] = s;
    }
}

// ---------- Kernel D2: broadcast over seqlen (g_ctx L2-resident, write-bound) ----------
__global__ void bcast_kernel(float4* __restrict__ out, int total4) {
    int i = blockIdx.x * 256 + threadIdx.x;
    if (i < total4)
        out[i] = reinterpret_cast<const float4*>(g_ctx)[i & (B * D / 4 - 1)];
}

extern "C" void kernel_launch(void* const* d_in, const int* in_sizes, int n_in,
                              void* d_out, int out_size) {
    // inputs: [0]=seqlen(int32), [1]=hidden f32 [1,B,H], [2]=contextvects f32 [B,D,C],
    //         [3]=W f32 [H,D], [4]=b f32 [H] (bias is softmax-invariant -> unused)
    const float* hid = (const float*)d_in[1];
    const float* ctx = (const float*)d_in[2];
    const float* W   = (const float*)d_in[3];

    vpart_kernel<<<dim3(8, HC), 128>>>(W, hid);
    vreduce_kernel<<<32, 256>>>();

    main_kernel<<<dim3(NCHB, B), 512>>>(ctx);

    combine_kernel<<<dim3(B, 8), 256>>>();

    const int total4 = out_size / 4;
    bcast_kernel<<<(total4 + 255) / 256, 256>>>((float4*)d_out, total4);
}

// round 8
// speedup vs baseline: 1.1043x; 1.1043x over previous
#include <cuda_runtime.h>

#define B    32
#define D    1024   // CTX_DIM
#define C    2048   // CTX_SIZE
#define H    1024   // HID
#define HC   32     // h-chunks in kernel A
#define HCH  (H/HC) // 32 h per chunk
#define CCH  16     // context columns per chunk
#define GCH  8      // chunks per CTA (flash-style running accumulation)
#define NCHB (C/(CCH*GCH))  // 16 CTA-columns per batch

// ---- scratch (no allocations allowed) ----
__device__ float g_pv[HC * B * D];       // 4 MB  partial v
__device__ float g_v[B * D];             // 128 KB v[b,d]
__device__ float g_pacc[B * NCHB * D];   // 2 MB per-CTA weighted partial sums
__device__ float g_pm[B * NCHB];         // per-CTA max
__device__ float g_pz[B * NCHB];         // per-CTA Z (unnormalized)

// ---------- Kernel A: partial v[b,d] = sum_{h in chunk} W[h,d]*hidden[b,h] ----------
__global__ void vpart_kernel(const float* __restrict__ W, const float* __restrict__ hid) {
    __shared__ float sh[B][HCH];
    const int tid = threadIdx.x;                 // 128 threads
    const int d   = blockIdx.x * 128 + tid;      // 8 d-tiles
    const int h0  = blockIdx.y * HCH;            // 32 h-chunks
    for (int i = tid; i < B * HCH; i += 128) {
        int b = i / HCH, h = i % HCH;
        sh[b][h] = hid[b * H + h0 + h];
    }
    __syncthreads();
    float acc[B];
#pragma unroll
    for (int b = 0; b < B; b++) acc[b] = 0.f;
#pragma unroll 8
    for (int h = 0; h < HCH; h++) {
        float w = W[(size_t)(h0 + h) * D + d];
#pragma unroll
        for (int b = 0; b < B; b++) acc[b] += w * sh[b][h];
    }
    float* outp = g_pv + (size_t)blockIdx.y * (B * D);
#pragma unroll
    for (int b = 0; b < B; b++) outp[b * D + d] = acc[b];
}

// ---------- Kernel B: reduce partials -> g_v (float4, MLP 8) ----------
__global__ void vreduce_kernel() {
    int i = blockIdx.x * 256 + threadIdx.x;      // 32 blocks x 256 -> 8192 float4
    const float4* src = reinterpret_cast<const float4*>(g_pv) + i;
    float4 s = make_float4(0.f, 0.f, 0.f, 0.f);
#pragma unroll 8
    for (int hc = 0; hc < HC; hc++) {
        float4 p = src[(size_t)hc * (B * D / 4)];
        s.x += p.x; s.y += p.y; s.z += p.z; s.w += p.w;
    }
    reinterpret_cast<float4*>(g_v)[i] = s;
}

// ---------- Kernel C: flash chunks, register accumulators, 2-sync tail ----------
__global__ void __launch_bounds__(512, 2) main_kernel(const float* __restrict__ ctx) {
    __shared__ float red[16 * 17];      // padded rows: conflict-free colsum reads

    const int tid  = threadIdx.x;       // 512
    const int lane = tid & 31;
    const int w    = tid >> 5;          // 0..15
    const int cq   = lane & 3;          // float4 column group 0..3
    const int r    = lane >> 2;         // 0..7
    const int b    = blockIdx.y;
    const int chg  = blockIdx.x;        // 0..NCHB-1
    const int colh = lane & 15;         // column this lane owns in softmax stage
    const int half = lane >> 4;         // 0..1

    const int drow = w * 8 + r;         // 0..127
    const float* base0 = ctx + (size_t)b * D * C + (size_t)drow * C
                       + chg * (CCH * GCH) + 4 * cq;

    float vr[8];
#pragma unroll
    for (int i = 0; i < 8; i++)
        vr[i] = __ldg(&g_v[b * D + i * 128 + drow]);

    float accR[8];                      // running weighted sums, rows 128*i+drow
#pragma unroll
    for (int i = 0; i < 8; i++) accR[i] = 0.f;
    float m_run = -1e30f, z_run = 0.f;

    for (int g = 0; g < GCH; g++) {
        const float* base = base0 + g * CCH;
        float4 x[8];
#pragma unroll
        for (int i = 0; i < 8; i++)
            x[i] = __ldcs(reinterpret_cast<const float4*>(base + (size_t)i * 128 * C));

        // Phase 1: partial scores for this warp's 64 rows
        float p0 = 0.f, p1 = 0.f, p2 = 0.f, p3 = 0.f;
#pragma unroll
        for (int i = 0; i < 8; i++) {
            p0 += x[i].x * vr[i];  p1 += x[i].y * vr[i];
            p2 += x[i].z * vr[i];  p3 += x[i].w * vr[i];
        }
#pragma unroll
        for (int o = 4; o <= 16; o <<= 1) {
            p0 += __shfl_xor_sync(0xffffffffu, p0, o);
            p1 += __shfl_xor_sync(0xffffffffu, p1, o);
            p2 += __shfl_xor_sync(0xffffffffu, p2, o);
            p3 += __shfl_xor_sync(0xffffffffu, p3, o);
        }
        if (lane < 4) {                 // r==0; cq==lane
            red[w * 17 + 4 * lane + 0] = p0;
            red[w * 17 + 4 * lane + 1] = p1;
            red[w * 17 + 4 * lane + 2] = p2;
            red[w * 17 + 4 * lane + 3] = p3;
        }
        __syncthreads();

        // Every warp redundantly: column sums over 16 warps + softmax stats
        float part = 0.f;
#pragma unroll
        for (int j = 0; j < 8; j++)
            part += red[(half * 8 + j) * 17 + colh];
        part += __shfl_xor_sync(0xffffffffu, part, 16);
        float m = part;
#pragma unroll
        for (int o = 1; o <= 8; o <<= 1) m = fmaxf(m, __shfl_xor_sync(0xffffffffu, m, o));
        float e = __expf(part - m);
        float z = e;
#pragma unroll
        for (int o = 1; o <= 8; o <<= 1) z += __shfl_xor_sync(0xffffffffu, z, o);

        // Each quad fetches its 4 column weights
        const float w0 = __shfl_sync(0xffffffffu, e, 4 * cq + 0, 16);
        const float w1 = __shfl_sync(0xffffffffu, e, 4 * cq + 1, 16);
        const float w2 = __shfl_sync(0xffffffffu, e, 4 * cq + 2, 16);
        const float w3 = __shfl_sync(0xffffffffu, e, 4 * cq + 3, 16);

        // Phase 2 + running rescale (register-resident)
        const float m_new = fmaxf(m_run, m);
        const float alpha = __expf(m_run - m_new);
        const float beta  = __expf(m - m_new);
#pragma unroll
        for (int i = 0; i < 8; i++) {
            float t = x[i].x * w0 + x[i].y * w1 + x[i].z * w2 + x[i].w * w3;
            t += __shfl_xor_sync(0xffffffffu, t, 1);
            t += __shfl_xor_sync(0xffffffffu, t, 2);
            accR[i] = accR[i] * alpha + t * beta;
        }
        z_run = z_run * alpha + z * beta;
        m_run = m_new;
        __syncthreads();                // WAR: red reused next chunk
    }

    if (cq == 0) {
        float* dst = g_pacc + (size_t)(b * NCHB + chg) * D;
#pragma unroll
        for (int i = 0; i < 8; i++) dst[i * 128 + drow] = accR[i];
    }
    if (tid == 0) { g_pm[b * NCHB + chg] = m_run; g_pz[b * NCHB + chg] = z_run; }
}

// ---------- Kernel D: combine chunk partials + broadcast over seqlen (fused) ----------
// grid (B, 8): block owns a 128-d slice; combines 16 chunks, writes all seqlen copies.
__global__ void combine_bcast_kernel(float4* __restrict__ out, int seqlen) {
    __shared__ float pm[NCHB], pz[NCHB], fsh[NCHB];
    __shared__ float inv_sh;
    __shared__ float4 part[8][32];
    __shared__ float4 res[32];
    const int b   = blockIdx.x;
    const int ds  = blockIdx.y;            // 0..7  d-slice (128 d's)
    const int tid = threadIdx.x;           // 256
    const int f4  = tid & 31;              // float4 within slice
    const int grp = tid >> 5;              // 0..7

    if (tid < NCHB) { pm[tid] = g_pm[b * NCHB + tid]; pz[tid] = g_pz[b * NCHB + tid]; }
    __syncthreads();
    if (tid < NCHB) {
        float M = -1e30f;
#pragma unroll
        for (int ch = 0; ch < NCHB; ch++) M = fmaxf(M, pm[ch]);
        fsh[tid] = __expf(pm[tid] - M);
        if (tid == 0) {
            float Z = 0.f;
#pragma unroll
            for (int ch = 0; ch < NCHB; ch++) Z += pz[ch] * __expf(pm[ch] - M);
            inv_sh = 1.0f / Z;
        }
    }
    __syncthreads();

    float4 a = make_float4(0.f, 0.f, 0.f, 0.f);
#pragma unroll
    for (int j = 0; j < 2; j++) {
        int ch = grp * 2 + j;
        float4 p = reinterpret_cast<const float4*>(
            g_pacc + (size_t)(b * NCHB + ch) * D + ds * 128)[f4];
        float f = fsh[ch];
        a.x += p.x * f; a.y += p.y * f; a.z += p.z * f; a.w += p.w * f;
    }
    part[grp][f4] = a;
    __syncthreads();

    if (tid < 32) {
        float4 s = make_float4(0.f, 0.f, 0.f, 0.f);
#pragma unroll
        for (int g = 0; g < 8; g++) {
            float4 p = part[g][tid];
            s.x += p.x; s.y += p.y; s.z += p.z; s.w += p.w;
        }
        const float inv = inv_sh;
        s.x *= inv; s.y *= inv; s.z *= inv; s.w *= inv;
        res[tid] = s;
    }
    __syncthreads();

    // Broadcast: each thread writes its float4 for seqlen/8 sequence positions.
    const float4 val = res[f4];
    float4* obase = out + (b * D + ds * 128) / 4 + f4;
    for (int s = grp; s < seqlen; s += 8)
        obase[(size_t)s * (B * D / 4)] = val;
}

extern "C" void kernel_launch(void* const* d_in, const int* in_sizes, int n_in,
                              void* d_out, int out_size) {
    // inputs: [0]=seqlen(int32), [1]=hidden f32 [1,B,H], [2]=contextvects f32 [B,D,C],
    //         [3]=W f32 [H,D], [4]=b f32 [H] (bias is softmax-invariant -> unused)
    const float* hid = (const float*)d_in[1];
    const float* ctx = (const float*)d_in[2];
    const float* W   = (const float*)d_in[3];
    const int seqlen = out_size / (B * D);

    vpart_kernel<<<dim3(8, HC), 128>>>(W, hid);
    vreduce_kernel<<<32, 256>>>();

    main_kernel<<<dim3(NCHB, B), 512>>>(ctx);

    combine_bcast_kernel<<<dim3(B, 8), 256>>>((float4*)d_out, seqlen);
}